// round 5
// baseline (speedup 1.0000x reference)
#include <cuda_runtime.h>

typedef unsigned long long ull;

// Scratch: processed states, natural layout [4096 rows x 16 floats] = 256 KB.
__device__ __align__(16) float g_P[4096 * 16];

__device__ __forceinline__ ull pack2(float lo, float hi) {
    ull r; asm("mov.b64 %0, {%1, %2};" : "=l"(r) : "f"(lo), "f"(hi)); return r;
}
__device__ __forceinline__ float hadd2(ull v) {
    float lo, hi; asm("mov.b64 {%0, %1}, %2;" : "=f"(lo), "=f"(hi) : "l"(v));
    return lo + hi;
}
// Packed dual-FMA (sm_100+ only; 2x fp32 FMA throughput vs FFMA-3reg)
__device__ __forceinline__ ull fma2(ull a, ull b, ull c) {
    ull d; asm("fma.rn.f32x2 %0, %1, %2, %3;" : "=l"(d) : "l"(a), "l"(b), "l"(c)); return d;
}

// ---------------------------------------------------------------------------
// Kernel 1: per-token quantum circuit -> g_P (natural layout)
// ---------------------------------------------------------------------------
__global__ void prep_kernel(const int* __restrict__ ids,
                            const int* __restrict__ mask,
                            const float* __restrict__ We,
                            const float* __restrict__ gates,
                            int BS, int depth, int S, int B) {
    __shared__ float sg[2 * 256];
    for (int i = threadIdx.x; i < depth * 256; i += blockDim.x) sg[i] = gates[i];
    __syncthreads();

    int m = blockIdx.x * blockDim.x + threadIdx.x;
    if (m >= BS) return;

    int tok = ids[m];
    float e[16], st[16];
    const float4* wr = (const float4*)(We + (size_t)tok * 16);
#pragma unroll
    for (int q = 0; q < 4; q++) {
        float4 v = wr[q];
        e[4*q+0] = v.x; e[4*q+1] = v.y; e[4*q+2] = v.z; e[4*q+3] = v.w;
    }
    float nrm = 0.f;
#pragma unroll
    for (int k = 0; k < 16; k++) nrm += e[k] * e[k];
    float inv = 1.f / (sqrtf(nrm) + 1e-12f);
#pragma unroll
    for (int k = 0; k < 16; k++) { e[k] *= inv; st[k] = e[k]; }

    for (int l = 0; l < depth; l++) {
        float tmp[16];
#pragma unroll
        for (int o = 0; o < 16; o++) {
            float acc = 0.f;
#pragma unroll
            for (int d = 0; d < 16; d++) acc += st[d] * sg[l*256 + o*16 + d];
            tmp[o] = acc;
        }
        float s2 = 0.f;
#pragma unroll
        for (int o = 0; o < 16; o++) {
            // (1-DECOHERENCE)*(1-DEPOL)*x + DEPOL/dim
            float x = tmp[o] * (0.99f * 0.99f) + (0.01f / 16.f);
            st[o] = x; s2 += x * x;
        }
        inv = 1.f / (sqrtf(s2) + 1e-12f);
#pragma unroll
        for (int o = 0; o < 16; o++) st[o] *= inv;
    }
#pragma unroll
    for (int k = 0; k < 16; k++) st[k] = st[k] * 0.99f + (0.01f / 16.f);

    int s = m % S;
    bool ap = true;
    for (int b = 0; b < B; b++) ap = ap && (mask[b * S + s] != 0);

    float4* dst = (float4*)(g_P + (size_t)m * 16);
#pragma unroll
    for (int q = 0; q < 4; q++) {
        dst[q] = make_float4(ap ? st[4*q]   : e[4*q],
                             ap ? st[4*q+1] : e[4*q+1],
                             ap ? st[4*q+2] : e[4*q+2],
                             ap ? st[4*q+3] : e[4*q+3]);
    }
}

// ---------------------------------------------------------------------------
// Kernel 2: out[4096, 32000] = P @ W_out^T + b_out
// 2 vocab columns per thread (W regs: 32 instead of 64) -> ~80 regs total ->
// 3 CTAs/SM resident (occ ~37%) so the FFMA2 pipe stays fed across per-warp
// stall bubbles. Accumulators paired over K:
//   acc_c = { sum_even p*w , sum_odd p*w }  -> one horizontal add per col.
// P rows arrive as natural {p_2k,p_2k+1} pairs via 4x broadcast LDS.128,
// double-buffered across rows. Output stores use evict-streaming (.cs).
// ---------------------------------------------------------------------------
#define MTILE 64

__global__ __launch_bounds__(256, 3)
void out_gemm_kernel(const float* __restrict__ Wout,
                     const float* __restrict__ bout,
                     float* __restrict__ out, int V) {
    __shared__ __align__(16) ull sP[MTILE * 8];   // 4 KB natural-pair tile

    int row0 = blockIdx.y * MTILE;
    // cooperative tile load: MTILE*16 floats = 256 float4 -> 1 per thread
    ((float4*)sP)[threadIdx.x] =
        ((const float4*)(g_P + (size_t)row0 * 16))[threadIdx.x];
    __syncthreads();

    int v0 = blockIdx.x * 512 + threadIdx.x * 2;
    if (v0 >= V) return;

    // W pairs are natural-adjacent: wc[k] = {W[col][2k], W[col][2k+1]}
    ull w0[8], w1[8];
    {
        const float4* wa = (const float4*)(Wout + (size_t)v0 * 16);
        const float4* wb = (const float4*)(Wout + (size_t)(v0 + 1) * 16);
#pragma unroll
        for (int q = 0; q < 4; q++) {
            float4 t = wa[q];
            w0[2*q+0] = pack2(t.x, t.y);
            w0[2*q+1] = pack2(t.z, t.w);
        }
#pragma unroll
        for (int q = 0; q < 4; q++) {
            float4 t = wb[q];
            w1[2*q+0] = pack2(t.x, t.y);
            w1[2*q+1] = pack2(t.z, t.w);
        }
    }
    // bias folded into acc init: hadd({b,0} + sums) = sum + b
    ull bi0 = pack2(bout[v0], 0.f);
    ull bi1 = pack2(bout[v0 + 1], 0.f);

    float* outp = out + (size_t)row0 * V + v0;

    ull pA[8], pB[8];
    // preload row 0 into A (4x broadcast LDS.128)
    {
        const ulonglong2* r = (const ulonglong2*)(sP);
#pragma unroll
        for (int q = 0; q < 4; q++) { ulonglong2 t = r[q]; pA[2*q] = t.x; pA[2*q+1] = t.y; }
    }

#pragma unroll 1
    for (int m = 0; m < MTILE; m += 2) {
        // prefetch row m+1 into B
        {
            const ulonglong2* r = (const ulonglong2*)(sP + (m + 1) * 8);
#pragma unroll
            for (int q = 0; q < 4; q++) { ulonglong2 t = r[q]; pB[2*q] = t.x; pB[2*q+1] = t.y; }
        }
        // compute row m from A
        {
            ull a0 = bi0, a1 = bi1;
#pragma unroll
            for (int k = 0; k < 8; k++) {
                ull p = pA[k];
                a0 = fma2(p, w0[k], a0);
                a1 = fma2(p, w1[k], a1);
            }
            float2 r = make_float2(hadd2(a0), hadd2(a1));
            __stcs((float2*)outp, r);
            outp += V;
        }
        // prefetch row m+2 into A
        if (m + 2 < MTILE) {
            const ulonglong2* r = (const ulonglong2*)(sP + (m + 2) * 8);
#pragma unroll
            for (int q = 0; q < 4; q++) { ulonglong2 t = r[q]; pA[2*q] = t.x; pA[2*q+1] = t.y; }
        }
        // compute row m+1 from B
        {
            ull a0 = bi0, a1 = bi1;
#pragma unroll
            for (int k = 0; k < 8; k++) {
                ull p = pB[k];
                a0 = fma2(p, w0[k], a0);
                a1 = fma2(p, w1[k], a1);
            }
            float2 r = make_float2(hadd2(a0), hadd2(a1));
            __stcs((float2*)outp, r);
            outp += V;
        }
    }
}

// ---------------------------------------------------------------------------
// Launch
// ---------------------------------------------------------------------------
extern "C" void kernel_launch(void* const* d_in, const int* in_sizes, int n_in,
                              void* d_out, int out_size) {
    const int*   ids   = (const int*)d_in[0];
    const int*   mask  = (const int*)d_in[1];
    const float* We    = (const float*)d_in[2];
    const float* gates = (const float*)d_in[3];
    const float* Wout  = (const float*)d_in[4];
    const float* bout  = (const float*)d_in[5];
    float* out = (float*)d_out;

    int BS    = in_sizes[0];          // B*S = 4096
    int V     = in_sizes[5];          // 32000
    int depth = in_sizes[3] / 256;    // 2
    int S     = 2048;                 // problem shape (fixed)
    int B     = BS / S;               // 2

    prep_kernel<<<(BS + 127) / 128, 128>>>(ids, mask, We, gates, BS, depth, S, B);

    dim3 grid((V + 511) / 512, BS / MTILE);
    out_gemm_kernel<<<grid, 256>>>(Wout, bout, out, V);
}

// round 6
// speedup vs baseline: 1.0996x; 1.0996x over previous
#include <cuda_runtime.h>

typedef unsigned long long ull;

// Scratch: processed states, natural layout [4096 rows x 16 floats] = 256 KB.
__device__ __align__(16) float g_P[4096 * 16];

__device__ __forceinline__ ull pack2(float lo, float hi) {
    ull r; asm("mov.b64 %0, {%1, %2};" : "=l"(r) : "f"(lo), "f"(hi)); return r;
}
__device__ __forceinline__ float hadd2(ull v) {
    float lo, hi; asm("mov.b64 {%0, %1}, %2;" : "=f"(lo), "=f"(hi) : "l"(v));
    return lo + hi;
}
// Packed dual-FMA (sm_100+ only; 2x fp32 FMA throughput vs FFMA-3reg)
__device__ __forceinline__ ull fma2(ull a, ull b, ull c) {
    ull d; asm("fma.rn.f32x2 %0, %1, %2, %3;" : "=l"(d) : "l"(a), "l"(b), "l"(c)); return d;
}

// ---------------------------------------------------------------------------
// Kernel 1: per-token quantum circuit -> g_P (natural layout)
// ---------------------------------------------------------------------------
__global__ void prep_kernel(const int* __restrict__ ids,
                            const int* __restrict__ mask,
                            const float* __restrict__ We,
                            const float* __restrict__ gates,
                            int BS, int depth, int S, int B) {
    __shared__ float sg[2 * 256];
    for (int i = threadIdx.x; i < depth * 256; i += blockDim.x) sg[i] = gates[i];
    __syncthreads();

    int m = blockIdx.x * blockDim.x + threadIdx.x;
    if (m >= BS) return;

    int tok = ids[m];
    float e[16], st[16];
    const float4* wr = (const float4*)(We + (size_t)tok * 16);
#pragma unroll
    for (int q = 0; q < 4; q++) {
        float4 v = wr[q];
        e[4*q+0] = v.x; e[4*q+1] = v.y; e[4*q+2] = v.z; e[4*q+3] = v.w;
    }
    float nrm = 0.f;
#pragma unroll
    for (int k = 0; k < 16; k++) nrm += e[k] * e[k];
    float inv = 1.f / (sqrtf(nrm) + 1e-12f);
#pragma unroll
    for (int k = 0; k < 16; k++) { e[k] *= inv; st[k] = e[k]; }

    for (int l = 0; l < depth; l++) {
        float tmp[16];
#pragma unroll
        for (int o = 0; o < 16; o++) {
            float acc = 0.f;
#pragma unroll
            for (int d = 0; d < 16; d++) acc += st[d] * sg[l*256 + o*16 + d];
            tmp[o] = acc;
        }
        float s2 = 0.f;
#pragma unroll
        for (int o = 0; o < 16; o++) {
            // (1-DECOHERENCE)*(1-DEPOL)*x + DEPOL/dim
            float x = tmp[o] * (0.99f * 0.99f) + (0.01f / 16.f);
            st[o] = x; s2 += x * x;
        }
        inv = 1.f / (sqrtf(s2) + 1e-12f);
#pragma unroll
        for (int o = 0; o < 16; o++) st[o] *= inv;
    }
#pragma unroll
    for (int k = 0; k < 16; k++) st[k] = st[k] * 0.99f + (0.01f / 16.f);

    int s = m % S;
    bool ap = true;
    for (int b = 0; b < B; b++) ap = ap && (mask[b * S + s] != 0);

    float4* dst = (float4*)(g_P + (size_t)m * 16);
#pragma unroll
    for (int q = 0; q < 4; q++) {
        dst[q] = make_float4(ap ? st[4*q]   : e[4*q],
                             ap ? st[4*q+1] : e[4*q+1],
                             ap ? st[4*q+2] : e[4*q+2],
                             ap ? st[4*q+3] : e[4*q+3]);
    }
}

// ---------------------------------------------------------------------------
// Kernel 2: out[4096, 32000] = P @ W_out^T + b_out
// 8 vocab columns per thread: the fixed per-row P smem traffic (4x broadcast
// LDS.128) is amortized over 144 fma-pipe cycles instead of 72 (R3) / 40 (R5)
// -> L1TEX (LDS+STG wavefront) pressure per fma halves. W lives entirely in
// registers (~205 regs, 1 CTA/SM); each warp carries 8 independent 8-deep
// FFMA2 chains so 2 warps/SMSP saturate the fma pipe. Accumulators paired
// over K: acc_c = {sum_even, sum_odd} -> 1 FADD per output. Streaming stores.
// ---------------------------------------------------------------------------
#define MTILE 64

__global__ __launch_bounds__(256, 1)
void out_gemm_kernel(const float* __restrict__ Wout,
                     const float* __restrict__ bout,
                     float* __restrict__ out, int V) {
    __shared__ __align__(16) ull sP[MTILE * 8];   // 4 KB natural-pair tile

    int row0 = blockIdx.y * MTILE;
    // cooperative tile load: MTILE*16 floats = 256 float4 -> 1 per thread
    ((float4*)sP)[threadIdx.x] =
        ((const float4*)(g_P + (size_t)row0 * 16))[threadIdx.x];
    __syncthreads();

    int v0 = blockIdx.x * 2048 + threadIdx.x * 8;
    if (v0 >= V) return;   // last column block is partially populated

    // W pairs are natural-adjacent: w[c][k] = {W[v0+c][2k], W[v0+c][2k+1]}
    ull w[8][8];
#pragma unroll
    for (int c = 0; c < 8; c++) {
        const float4* wc = (const float4*)(Wout + (size_t)(v0 + c) * 16);
#pragma unroll
        for (int q = 0; q < 4; q++) {
            float4 t = wc[q];
            w[c][2*q+0] = pack2(t.x, t.y);
            w[c][2*q+1] = pack2(t.z, t.w);
        }
    }
    // bias folded into acc init: hadd({b,0} + sums) = sum + b
    ull binit[8];
#pragma unroll
    for (int c = 0; c < 8; c++) binit[c] = pack2(bout[v0 + c], 0.f);

    float* outp = out + (size_t)row0 * V + v0;

    ull pA[8], pB[8];
    // preload row 0 into A (4x broadcast LDS.128)
    {
        const ulonglong2* r = (const ulonglong2*)(sP);
#pragma unroll
        for (int q = 0; q < 4; q++) { ulonglong2 t = r[q]; pA[2*q] = t.x; pA[2*q+1] = t.y; }
    }

#pragma unroll 1
    for (int m = 0; m < MTILE; m += 2) {
        // prefetch row m+1 into B
        {
            const ulonglong2* r = (const ulonglong2*)(sP + (m + 1) * 8);
#pragma unroll
            for (int q = 0; q < 4; q++) { ulonglong2 t = r[q]; pB[2*q] = t.x; pB[2*q+1] = t.y; }
        }
        // compute row m from A
        {
            ull a[8];
#pragma unroll
            for (int c = 0; c < 8; c++) a[c] = binit[c];
#pragma unroll
            for (int k = 0; k < 8; k++) {
                ull p = pA[k];
#pragma unroll
                for (int c = 0; c < 8; c++) a[c] = fma2(p, w[c][k], a[c]);
            }
            float4 r1 = make_float4(hadd2(a[0]), hadd2(a[1]), hadd2(a[2]), hadd2(a[3]));
            float4 r2 = make_float4(hadd2(a[4]), hadd2(a[5]), hadd2(a[6]), hadd2(a[7]));
            __stcs((float4*)outp, r1);
            __stcs((float4*)(outp + 4), r2);
            outp += V;
        }
        // prefetch row m+2 into A
        if (m + 2 < MTILE) {
            const ulonglong2* r = (const ulonglong2*)(sP + (m + 2) * 8);
#pragma unroll
            for (int q = 0; q < 4; q++) { ulonglong2 t = r[q]; pA[2*q] = t.x; pA[2*q+1] = t.y; }
        }
        // compute row m+1 from B
        {
            ull a[8];
#pragma unroll
            for (int c = 0; c < 8; c++) a[c] = binit[c];
#pragma unroll
            for (int k = 0; k < 8; k++) {
                ull p = pB[k];
#pragma unroll
                for (int c = 0; c < 8; c++) a[c] = fma2(p, w[c][k], a[c]);
            }
            float4 r1 = make_float4(hadd2(a[0]), hadd2(a[1]), hadd2(a[2]), hadd2(a[3]));
            float4 r2 = make_float4(hadd2(a[4]), hadd2(a[5]), hadd2(a[6]), hadd2(a[7]));
            __stcs((float4*)outp, r1);
            __stcs((float4*)(outp + 4), r2);
            outp += V;
        }
    }
}

// ---------------------------------------------------------------------------
// Launch
// ---------------------------------------------------------------------------
extern "C" void kernel_launch(void* const* d_in, const int* in_sizes, int n_in,
                              void* d_out, int out_size) {
    const int*   ids   = (const int*)d_in[0];
    const int*   mask  = (const int*)d_in[1];
    const float* We    = (const float*)d_in[2];
    const float* gates = (const float*)d_in[3];
    const float* Wout  = (const float*)d_in[4];
    const float* bout  = (const float*)d_in[5];
    float* out = (float*)d_out;

    int BS    = in_sizes[0];          // B*S = 4096
    int V     = in_sizes[5];          // 32000
    int depth = in_sizes[3] / 256;    // 2
    int S     = 2048;                 // problem shape (fixed)
    int B     = BS / S;               // 2

    prep_kernel<<<(BS + 127) / 128, 128>>>(ids, mask, We, gates, BS, depth, S, B);

    // 16 column blocks of 2048 (last block 75% populated), 64 row tiles
    dim3 grid((V + 2047) / 2048, BS / MTILE);
    out_gemm_kernel<<<grid, 256>>>(Wout, bout, out, V);
}

// round 8
// speedup vs baseline: 1.1036x; 1.0036x over previous
#include <cuda_runtime.h>
#include <cuda_bf16.h>
#include <cstdint>

typedef unsigned long long ull;

// ---------------------------------------------------------------------------
// Scratch (bf16 hi/lo-split GEMM operands, K=64 per row = 128 B)
//   g_A[m][64]: [Phi(16) | Phi(16) | Plo(16) | 1,1,0...]
//   g_W[v][64]: [Whi(16) | Wlo(16) | Whi(16) | bias_hi,bias_lo,0...]
// D = Phi*Whi + Phi*Wlo + Plo*Whi + bias  (fp32 accum; lo*lo term ~2^-18)
// ---------------------------------------------------------------------------
__device__ __align__(16) __nv_bfloat16 g_A[4096 * 64];
__device__ __align__(16) __nv_bfloat16 g_W[32000 * 64];

__device__ __forceinline__ uint32_t smem_u32(const void* p) {
    uint32_t a;
    asm("{ .reg .u64 t; cvta.to.shared.u64 t, %1; cvt.u32.u64 %0, t; }"
        : "=r"(a) : "l"(p));
    return a;
}
__device__ __forceinline__ void bf16_split(float x, __nv_bfloat16& hi, __nv_bfloat16& lo) {
    hi = __float2bfloat16(x);
    lo = __float2bfloat16(x - __bfloat162float(hi));
}

// ---------------------------------------------------------------------------
// Kernel 1: per-token quantum circuit -> g_A rows (bf16 split layout)
// ---------------------------------------------------------------------------
__global__ void prep_kernel(const int* __restrict__ ids,
                            const int* __restrict__ mask,
                            const float* __restrict__ We,
                            const float* __restrict__ gates,
                            int BS, int depth, int S, int B) {
    __shared__ float sg[2 * 256];
    for (int i = threadIdx.x; i < depth * 256; i += blockDim.x) sg[i] = gates[i];
    __syncthreads();

    int m = blockIdx.x * blockDim.x + threadIdx.x;
    if (m >= BS) return;

    int tok = ids[m];
    float e[16], st[16];
    const float4* wr = (const float4*)(We + (size_t)tok * 16);
#pragma unroll
    for (int q = 0; q < 4; q++) {
        float4 v = wr[q];
        e[4*q+0] = v.x; e[4*q+1] = v.y; e[4*q+2] = v.z; e[4*q+3] = v.w;
    }
    float nrm = 0.f;
#pragma unroll
    for (int k = 0; k < 16; k++) nrm += e[k] * e[k];
    float inv = 1.f / (sqrtf(nrm) + 1e-12f);
#pragma unroll
    for (int k = 0; k < 16; k++) { e[k] *= inv; st[k] = e[k]; }

    for (int l = 0; l < depth; l++) {
        float tmp[16];
#pragma unroll
        for (int o = 0; o < 16; o++) {
            float acc = 0.f;
#pragma unroll
            for (int d = 0; d < 16; d++) acc += st[d] * sg[l*256 + o*16 + d];
            tmp[o] = acc;
        }
        float s2 = 0.f;
#pragma unroll
        for (int o = 0; o < 16; o++) {
            float x = tmp[o] * (0.99f * 0.99f) + (0.01f / 16.f);
            st[o] = x; s2 += x * x;
        }
        inv = 1.f / (sqrtf(s2) + 1e-12f);
#pragma unroll
        for (int o = 0; o < 16; o++) st[o] *= inv;
    }
#pragma unroll
    for (int k = 0; k < 16; k++) st[k] = st[k] * 0.99f + (0.01f / 16.f);

    int s = m % S;
    bool ap = true;
    for (int b = 0; b < B; b++) ap = ap && (mask[b * S + s] != 0);

    __nv_bfloat16* row = g_A + (size_t)m * 64;
#pragma unroll
    for (int k = 0; k < 16; k++) {
        float v = ap ? st[k] : e[k];
        __nv_bfloat16 hi, lo; bf16_split(v, hi, lo);
        row[k] = hi; row[16 + k] = hi; row[32 + k] = lo;
    }
    row[48] = __float2bfloat16(1.0f);
    row[49] = __float2bfloat16(1.0f);
#pragma unroll
    for (int k = 50; k < 64; k++) row[k] = __float2bfloat16(0.0f);
}

// ---------------------------------------------------------------------------
// Kernel 1b: W_out + bias -> g_W rows (bf16 split layout)
// ---------------------------------------------------------------------------
__global__ void wconv_kernel(const float* __restrict__ Wout,
                             const float* __restrict__ bout, int V) {
    int v = blockIdx.x * blockDim.x + threadIdx.x;
    if (v >= V) return;
    const float* wr = Wout + (size_t)v * 16;
    __nv_bfloat16* row = g_W + (size_t)v * 64;
#pragma unroll
    for (int k = 0; k < 16; k++) {
        __nv_bfloat16 hi, lo; bf16_split(wr[k], hi, lo);
        row[k] = hi; row[16 + k] = lo; row[32 + k] = hi;
    }
    __nv_bfloat16 bh, bl; bf16_split(bout[v], bh, bl);
    row[48] = bh; row[49] = bl;
#pragma unroll
    for (int k = 50; k < 64; k++) row[k] = __float2bfloat16(0.0f);
}

// ---------------------------------------------------------------------------
// Kernel 2: HMMA bf16 GEMM (mma.sync.m16n8k16 — no tcgen05 / no 'a' target).
// CTA: 256 threads / 8 warps (2x4), tile 128 rows x 128 vocab, K=64 (4 steps).
// smem tiles use 72-bf16 (144B) row stride: 144 mod 128 = 16 so the 8 row
// addresses of every ldmatrix land on 8 distinct 16B bank groups (no swizzle
// needed). Epilogue stores fp32 fragments directly: each lane-quad writes a
// contiguous 32B sector. Streaming stores keep W/A L2-resident.
// ---------------------------------------------------------------------------
#define SA 72   // smem row stride in bf16

__global__ __launch_bounds__(256)
void hmma_gemm_kernel(float* __restrict__ out, int V) {
    __shared__ __align__(16) __nv_bfloat16 sA[128 * SA];
    __shared__ __align__(16) __nv_bfloat16 sB[128 * SA];

    int tid = threadIdx.x, wid = tid >> 5, lane = tid & 31;
    int row0 = blockIdx.y * 128;
    int v0   = blockIdx.x * 128;

    // cooperative tile loads: 128 rows x 64 bf16 = 1024 uint4 each
    {
        const uint4* srcA = (const uint4*)(g_A + (size_t)row0 * 64);
        const uint4* srcB = (const uint4*)(g_W + (size_t)v0 * 64);
#pragma unroll
        for (int i = tid; i < 1024; i += 256) {
            int r = i >> 3, c = i & 7;
            *(uint4*)(sA + r * SA + c * 8) = srcA[i];
            *(uint4*)(sB + r * SA + c * 8) = srcB[i];
        }
    }
    __syncthreads();

    int wm = wid >> 2;        // 0..1 : 64-row half
    int wn = wid & 3;         // 0..3 : 32-col quarter

    // ldmatrix lane->address mapping
    //  A (.x4, 16x16): matrix m = lane>>3; row += (m&1)*8; col += (m>>1)*8
    int aRowL = (lane & 7) + ((lane >> 3) & 1) * 8;
    int aColH = ((lane >> 4) & 1) * 8;
    //  B (.x2, 8x16): lanes 0-15; m = (lane>>3)&1 selects k-half
    int lb = lane & 15;
    int bRowL = lb & 7;
    int bColH = ((lb >> 3) & 1) * 8;

    uint32_t aBase = smem_u32(sA);
    uint32_t bBase = smem_u32(sB);

    float c[4][4][4];
#pragma unroll
    for (int mt = 0; mt < 4; mt++)
#pragma unroll
        for (int nt = 0; nt < 4; nt++)
#pragma unroll
            for (int j = 0; j < 4; j++) c[mt][nt][j] = 0.f;

#pragma unroll
    for (int k = 0; k < 4; k++) {
        uint32_t a[4][4], b[4][2];
#pragma unroll
        for (int mt = 0; mt < 4; mt++) {
            uint32_t addr = aBase +
                (uint32_t)(((wm * 64 + mt * 16 + aRowL) * SA + k * 16 + aColH) * 2);
            asm volatile("ldmatrix.sync.aligned.m8n8.x4.shared.b16 {%0,%1,%2,%3}, [%4];"
                         : "=r"(a[mt][0]), "=r"(a[mt][1]), "=r"(a[mt][2]), "=r"(a[mt][3])
                         : "r"(addr));
        }
#pragma unroll
        for (int nt = 0; nt < 4; nt++) {
            uint32_t addr = bBase +
                (uint32_t)(((wn * 32 + nt * 8 + bRowL) * SA + k * 16 + bColH) * 2);
            asm volatile("ldmatrix.sync.aligned.m8n8.x2.shared.b16 {%0,%1}, [%2];"
                         : "=r"(b[nt][0]), "=r"(b[nt][1]) : "r"(addr));
        }
#pragma unroll
        for (int mt = 0; mt < 4; mt++)
#pragma unroll
            for (int nt = 0; nt < 4; nt++)
                asm volatile(
                    "mma.sync.aligned.m16n8k16.row.col.f32.bf16.bf16.f32 "
                    "{%0,%1,%2,%3}, {%4,%5,%6,%7}, {%8,%9}, {%0,%1,%2,%3};"
                    : "+f"(c[mt][nt][0]), "+f"(c[mt][nt][1]),
                      "+f"(c[mt][nt][2]), "+f"(c[mt][nt][3])
                    : "r"(a[mt][0]), "r"(a[mt][1]), "r"(a[mt][2]), "r"(a[mt][3]),
                      "r"(b[nt][0]), "r"(b[nt][1]));
    }

    // epilogue: fragment rows lane/4 and lane/4+8, cols (lane%4)*2..+1
    int rr = lane >> 2, cc = (lane & 3) * 2;
#pragma unroll
    for (int mt = 0; mt < 4; mt++) {
        int grow = row0 + wm * 64 + mt * 16 + rr;
#pragma unroll
        for (int nt = 0; nt < 4; nt++) {
            int gcol = v0 + wn * 32 + nt * 8 + cc;
            __stcs((float2*)(out + (size_t)grow * V + gcol),
                   make_float2(c[mt][nt][0], c[mt][nt][1]));
            __stcs((float2*)(out + (size_t)(grow + 8) * V + gcol),
                   make_float2(c[mt][nt][2], c[mt][nt][3]));
        }
    }
}

// ---------------------------------------------------------------------------
// Launch
// ---------------------------------------------------------------------------
extern "C" void kernel_launch(void* const* d_in, const int* in_sizes, int n_in,
                              void* d_out, int out_size) {
    const int*   ids   = (const int*)d_in[0];
    const int*   mask  = (const int*)d_in[1];
    const float* We    = (const float*)d_in[2];
    const float* gates = (const float*)d_in[3];
    const float* Wout  = (const float*)d_in[4];
    const float* bout  = (const float*)d_in[5];
    float* out = (float*)d_out;

    int BS    = in_sizes[0];          // 4096
    int V     = in_sizes[5];          // 32000
    int depth = in_sizes[3] / 256;    // 2
    int S     = 2048;
    int B     = BS / S;

    prep_kernel<<<(BS + 127) / 128, 128>>>(ids, mask, We, gates, BS, depth, S, B);
    wconv_kernel<<<(V + 127) / 128, 128>>>(Wout, bout, V);

    dim3 grid(V / 128, BS / 128);     // (250, 32)
    hmma_gemm_kernel<<<grid, 256>>>(out, V);
}